// round 1
// baseline (speedup 1.0000x reference)
#include <cuda_runtime.h>

// GridSample1d: N=64, C=64, L_in=4096, L_out=8192
// align_corners=True, padding=border, fp32.
//
// Strategy: block = (n, group of CG channels). Stage CG input rows (16KB each)
// into SMEM via coalesced float4 loads; random bilinear gather is then served
// by the SMEM crossbar (~4 cyc/warp at random conflict degree) instead of
// L1tex wavefront-per-line (~28 cyc/warp). Grid index math amortized over CG
// channels; all GMEM traffic (input stage, grid read, output store) is
// perfectly coalesced float4.

#define N_B     64
#define C_TOT   64
#define L_IN    4096
#define L_OUT   8192
#define CG      4          // channels per block
#define THREADS 256
#define VEC     4          // l_out positions per thread per iteration

__global__ __launch_bounds__(THREADS)
void gs1d_kernel(const float* __restrict__ inp,
                 const float* __restrict__ grid,
                 float* __restrict__ out)
{
    extern __shared__ float s_in[];   // [CG][L_IN] = 64 KB

    const int blk = blockIdx.x;
    const int n  = blk / (C_TOT / CG);
    const int cg = blk % (C_TOT / CG);
    const int c0 = cg * CG;

    // ---- stage CG input rows into SMEM (coalesced float4) ----
    {
        const float4* src = reinterpret_cast<const float4*>(
            inp + ((size_t)n * C_TOT + c0) * L_IN);
        float4* dst = reinterpret_cast<float4*>(s_in);
        #pragma unroll
        for (int i = threadIdx.x; i < CG * L_IN / 4; i += THREADS)
            dst[i] = src[i];
    }
    __syncthreads();

    const float* grow  = grid + (size_t)n * L_OUT;
    float*       obase = out  + ((size_t)n * C_TOT + c0) * L_OUT;

    const float scale = 0.5f * (float)(L_IN - 1);

    #pragma unroll 2
    for (int it = 0; it < L_OUT / (THREADS * VEC); ++it) {
        const int l0 = it * (THREADS * VEC) + threadIdx.x * VEC;

        // coalesced grid read (4 samples)
        const float4 g = *reinterpret_cast<const float4*>(grow + l0);
        const float xs[4] = {g.x, g.y, g.z, g.w};

        int   i0[4], i1[4];
        float w0[4], w1[4];
        #pragma unroll
        for (int j = 0; j < 4; ++j) {
            float x = (xs[j] + 1.0f) * scale;           // unnormalize (align_corners)
            x = fminf(fmaxf(x, 0.0f), (float)(L_IN - 1)); // border clamp
            float xf = floorf(x);
            i0[j] = (int)xf;
            w1[j] = x - xf;
            w0[j] = 1.0f - w1[j];
            i1[j] = min(i0[j] + 1, L_IN - 1);
        }

        #pragma unroll
        for (int c = 0; c < CG; ++c) {
            const float* srow = s_in + c * L_IN;
            float r[4];
            #pragma unroll
            for (int j = 0; j < 4; ++j) {
                float v0 = srow[i0[j]];
                float v1 = srow[i1[j]];
                r[j] = w0[j] * v0 + w1[j] * v1;
            }
            float4 o = make_float4(r[0], r[1], r[2], r[3]);
            *reinterpret_cast<float4*>(obase + (size_t)c * L_OUT + l0) = o;
        }
    }
}

extern "C" void kernel_launch(void* const* d_in, const int* in_sizes, int n_in,
                              void* d_out, int out_size)
{
    const float* inp  = (const float*)d_in[0];  // [64, 64, 4096]
    const float* grid = (const float*)d_in[1];  // [64, 8192]
    float*       out  = (float*)d_out;          // [64, 64, 8192]

    const int smem_bytes = CG * L_IN * sizeof(float);  // 64 KB (needs opt-in)
    cudaFuncSetAttribute(gs1d_kernel,
                         cudaFuncAttributeMaxDynamicSharedMemorySize,
                         smem_bytes);

    const int blocks = N_B * (C_TOT / CG);  // 1024
    gs1d_kernel<<<blocks, THREADS, smem_bytes>>>(inp, grid, out);
}

// round 2
// speedup vs baseline: 1.1490x; 1.1490x over previous
#include <cuda_runtime.h>
#include <cstdint>

// GridSample1d: N=64, C=64, L_in=4096, L_out=8192, fp32,
// align_corners=True, padding=border.
//
// R2: channel-interleaved float4 SMEM layout with SW128-style swizzle.
//  - s4[i] = {ch0[i], ch1[i], ch2[i], ch3[i]}  (one LDS.128 = 1 tap x 4 channels)
//  - gather per l_out: 2x LDS.128 (v0, v1) instead of 8x conflicted LDS.32
//  - XOR swizzle makes the transposed staging STS.128 (64B lane stride)
//    conflict-free; gather addresses are random so swizzle costs nothing there.
//  - 512 threads/block, 64KB smem -> up to 3 blocks / 48 warps per SM.

#define N_B     64
#define C_TOT   64
#define L_IN    4096
#define L_OUT   8192
#define CG      4          // channels per block (packed in one float4)
#define THREADS 512
#define VEC     2          // l_out positions per thread per iteration

__device__ __forceinline__ uint32_t swz(uint32_t byte_off) {
    // permute bits [4:6] by bits [7:9]; preserves 16B alignment
    return byte_off ^ ((byte_off >> 3) & 0x70);
}

__global__ __launch_bounds__(THREADS)
void gs1d_kernel(const float* __restrict__ inp,
                 const float* __restrict__ grid,
                 float* __restrict__ out)
{
    extern __shared__ char s_raw[];   // 4096 float4 = 64 KB, swizzled

    const int blk = blockIdx.x;
    const int n  = blk / (C_TOT / CG);
    const int cg = blk % (C_TOT / CG);
    const int c0 = cg * CG;

    // ---- stage: transpose [CG][L_IN] -> interleaved float4[L_IN], swizzled ----
    {
        const float* base = inp + ((size_t)n * C_TOT + c0) * L_IN;
        // each thread handles chunks of 4 consecutive i
        for (int i0 = threadIdx.x * 4; i0 < L_IN; i0 += THREADS * 4) {
            float4 a[CG];
            #pragma unroll
            for (int c = 0; c < CG; ++c)
                a[c] = *reinterpret_cast<const float4*>(base + (size_t)c * L_IN + i0);
            #pragma unroll
            for (int k = 0; k < 4; ++k) {
                float4 v;
                v.x = ((const float*)&a[0])[k];
                v.y = ((const float*)&a[1])[k];
                v.z = ((const float*)&a[2])[k];
                v.w = ((const float*)&a[3])[k];
                *reinterpret_cast<float4*>(s_raw + swz((uint32_t)(i0 + k) * 16u)) = v;
            }
        }
    }
    __syncthreads();

    const float* grow  = grid + (size_t)n * L_OUT;
    float*       obase = out  + ((size_t)n * C_TOT + c0) * L_OUT;

    const float scale = 0.5f * (float)(L_IN - 1);

    for (int it = 0; it < L_OUT / (THREADS * VEC); ++it) {
        const int l0 = it * (THREADS * VEC) + threadIdx.x * VEC;

        const float2 g = *reinterpret_cast<const float2*>(grow + l0);
        const float xs[VEC] = {g.x, g.y};

        float r[CG][VEC];

        #pragma unroll
        for (int j = 0; j < VEC; ++j) {
            float x = (xs[j] + 1.0f) * scale;               // align_corners
            x = fminf(fmaxf(x, 0.0f), (float)(L_IN - 1));   // border clamp
            float xf = floorf(x);
            int   i0 = (int)xf;
            float w1 = x - xf;
            float w0 = 1.0f - w1;
            int   i1 = min(i0 + 1, L_IN - 1);

            const float4 v0 = *reinterpret_cast<const float4*>(
                s_raw + swz((uint32_t)i0 * 16u));
            const float4 v1 = *reinterpret_cast<const float4*>(
                s_raw + swz((uint32_t)i1 * 16u));

            r[0][j] = w0 * v0.x + w1 * v1.x;
            r[1][j] = w0 * v0.y + w1 * v1.y;
            r[2][j] = w0 * v0.z + w1 * v1.z;
            r[3][j] = w0 * v0.w + w1 * v1.w;
        }

        #pragma unroll
        for (int c = 0; c < CG; ++c) {
            float2 o = make_float2(r[c][0], r[c][1]);
            *reinterpret_cast<float2*>(obase + (size_t)c * L_OUT + l0) = o;
        }
    }
}

extern "C" void kernel_launch(void* const* d_in, const int* in_sizes, int n_in,
                              void* d_out, int out_size)
{
    const float* inp  = (const float*)d_in[0];  // [64, 64, 4096]
    const float* grid = (const float*)d_in[1];  // [64, 8192]
    float*       out  = (float*)d_out;          // [64, 64, 8192]

    const int smem_bytes = L_IN * (int)sizeof(float4);  // 64 KB
    cudaFuncSetAttribute(gs1d_kernel,
                         cudaFuncAttributeMaxDynamicSharedMemorySize,
                         smem_bytes);

    const int blocks = N_B * (C_TOT / CG);  // 1024
    gs1d_kernel<<<blocks, THREADS, smem_bytes>>>(inp, grid, out);
}